// round 15
// baseline (speedup 1.0000x reference)
#include <cuda_runtime.h>

#define IMG_W 200
#define CHAN 512
#define NF4  (CHAN / 4)
#define POOL 7
#define NROI 300
#define NPOS (NROI * POOL * POOL)   // 14700

// 256-thread blocks, each covering TWO pool positions: half-block (4 warps)
// per position. Per-thread work/registers identical to the 128-thread best
// variant (~28 regs, one position each), but half the blocks -> half the
// block dispatch + tail overhead.
__global__ void __launch_bounds__(256) roi_pool_kernel(
    const float* __restrict__ img,   // [200,200,512]
    const int*   __restrict__ rois,  // [300,4] = (x,y,w,h)
    float*       __restrict__ out)   // [300,7,7,512]
{
    const int half = threadIdx.x >> 7;               // 0 or 1
    const int c4   = threadIdx.x & 127;              // float4 lane
    const int pos  = blockIdx.x * 2 + half;          // 0..14699

    const int roi = pos / (POOL * POOL);
    const int pp  = pos % (POOL * POOL);
    const int gy  = pp / POOL;
    const int gx  = pp % POOL;

    const int4 r = __ldg((const int4*)rois + roi);
    const int x0 = r.x, y0 = r.y, w = r.z, h = r.w;

    // Match reference numerics exactly.
    const float ys = (float)y0 + (float)gy * ((float)h / (float)POOL);
    const float xs = (float)x0 + (float)gx * ((float)w / (float)POOL);
    const int ty = (int)floorf(ys);
    const int tx = (int)floorf(xs);
    const float fy = ys - (float)ty;
    const float fx = xs - (float)tx;
    const int by = min(ty + 1, y0 + h - 1);
    const int bx = min(tx + 1, x0 + w - 1);

    // Zero-weight corners alias an already-loaded line (branch-free, L1 hit,
    // no extra L2 traffic; weight is exactly 0 so the value is irrelevant).
    int o00 = (ty * IMG_W + tx) * CHAN;
    int o01 = (ty * IMG_W + bx) * CHAN;
    int o10 = (by * IMG_W + tx) * CHAN;
    int o11 = (by * IMG_W + bx) * CHAN;

    const bool lx = (fx != 0.0f);
    const bool ly = (fy != 0.0f);
    o01 = lx ? o01 : o00;
    o10 = ly ? o10 : o00;
    o11 = (lx && ly) ? o11 : o01;

    const float4* base = (const float4*)img;

    const float4 v00 = __ldg(base + (o00 >> 2) + c4);
    const float4 v01 = __ldg(base + (o01 >> 2) + c4);
    const float4 v10 = __ldg(base + (o10 >> 2) + c4);
    const float4 v11 = __ldg(base + (o11 >> 2) + c4);

    const float omfx = 1.0f - fx;
    const float omfy = 1.0f - fy;

    float4 res;
    res.x = omfy * (omfx * v00.x + fx * v01.x) + fy * (omfx * v10.x + fx * v11.x);
    res.y = omfy * (omfx * v00.y + fx * v01.y) + fy * (omfx * v10.y + fx * v11.y);
    res.z = omfy * (omfx * v00.z + fx * v01.z) + fy * (omfx * v10.z + fx * v11.z);
    res.w = omfy * (omfx * v00.w + fx * v01.w) + fy * (omfx * v10.w + fx * v11.w);

    ((float4*)out)[pos * NF4 + c4] = res;
}

extern "C" void kernel_launch(void* const* d_in, const int* in_sizes, int n_in,
                              void* d_out, int out_size) {
    const float* img  = (const float*)d_in[0];
    const int*   rois = (const int*)d_in[1];
    float*       out  = (float*)d_out;

    roi_pool_kernel<<<NPOS / 2, 256>>>(img, rois, out);
}

// round 16
// speedup vs baseline: 1.1754x; 1.1754x over previous
#include <cuda_runtime.h>

#define IMG_W 200
#define CHAN 512
#define POOL 7
#define NROI 300

// grid = (49, 300): blockIdx.x = pool position (gy*7+gx), blockIdx.y = roi.
// 128 threads, one float4 lane each. All address setup is block-uniform.
// Zero-weight corners alias an already-loaded line (branch-free, L1 hit,
// no extra L2 traffic; weight is exactly 0 so the value is irrelevant).
//
// Session verdict (15 experiments): this kernel sits at the measured
// latency x L1tex-wavefront equilibrium (~12.8us ncu) for this problem on
// sm_103a. TMA-bulk, cp.async, smem staging, constant bank, streaming
// stores, L1-reuse tilings, MLP scaling, and block-shape changes were all
// neutral or worse.
__global__ void __launch_bounds__(128) roi_pool_kernel(
    const float* __restrict__ img,   // [200,200,512]
    const int*   __restrict__ rois,  // [300,4] = (x,y,w,h)
    float*       __restrict__ out)   // [300,7,7,512]
{
    const int gx  = blockIdx.x % POOL;
    const int gy  = blockIdx.x / POOL;
    const int roi = blockIdx.y;

    const int4 r = __ldg((const int4*)rois + roi);
    const int x0 = r.x, y0 = r.y, w = r.z, h = r.w;

    // Match reference numerics exactly.
    const float ys = (float)y0 + (float)gy * ((float)h / (float)POOL);
    const float xs = (float)x0 + (float)gx * ((float)w / (float)POOL);
    const int ty = (int)floorf(ys);
    const int tx = (int)floorf(xs);
    const float fy = ys - (float)ty;
    const float fx = xs - (float)tx;
    const int by = min(ty + 1, y0 + h - 1);
    const int bx = min(tx + 1, x0 + w - 1);

    // 32-bit element offsets (max 200*200*512 < 2^31). Block-uniform.
    int o00 = (ty * IMG_W + tx) * CHAN;
    int o01 = (ty * IMG_W + bx) * CHAN;
    int o10 = (by * IMG_W + tx) * CHAN;
    int o11 = (by * IMG_W + bx) * CHAN;

    const bool lx = (fx != 0.0f);
    const bool ly = (fy != 0.0f);
    o01 = lx ? o01 : o00;
    o10 = ly ? o10 : o00;
    o11 = (lx && ly) ? o11 : o01;

    const int c4 = threadIdx.x;          // float4 lane 0..127
    const float4* base = (const float4*)img;

    const float4 v00 = __ldg(base + (o00 >> 2) + c4);
    const float4 v01 = __ldg(base + (o01 >> 2) + c4);
    const float4 v10 = __ldg(base + (o10 >> 2) + c4);
    const float4 v11 = __ldg(base + (o11 >> 2) + c4);

    const float omfx = 1.0f - fx;
    const float omfy = 1.0f - fy;

    float4 res;
    res.x = omfy * (omfx * v00.x + fx * v01.x) + fy * (omfx * v10.x + fx * v11.x);
    res.y = omfy * (omfx * v00.y + fx * v01.y) + fy * (omfx * v10.y + fx * v11.y);
    res.z = omfy * (omfx * v00.z + fx * v01.z) + fy * (omfx * v10.z + fx * v11.z);
    res.w = omfy * (omfx * v00.w + fx * v01.w) + fy * (omfx * v10.w + fx * v11.w);

    const int opos = (roi * (POOL * POOL) + blockIdx.x) * (CHAN / 4) + c4;
    ((float4*)out)[opos] = res;
}

extern "C" void kernel_launch(void* const* d_in, const int* in_sizes, int n_in,
                              void* d_out, int out_size) {
    const float* img  = (const float*)d_in[0];
    const int*   rois = (const int*)d_in[1];
    float*       out  = (float*)d_out;

    dim3 grid(POOL * POOL, NROI);   // (49, 300)
    roi_pool_kernel<<<grid, 128>>>(img, rois, out);
}